// round 3
// baseline (speedup 1.0000x reference)
#include <cuda_runtime.h>

// Problem constants
#define B_TOT   4096
#define F0N     39
#define DN      16
#define K0TOT   (39*39)   // 1521
#define K1TOT   (39*64)   // 2496
#define BM      128       // 8 batches * 16 d
#define BN      128
#define BK      16
#define NTHREADS 256

// h buffer between layers: [b][j][d], j in 0..63
__device__ float g_h[B_TOT * 64 * DN];

// LAYER 0: h == x (FK=39), writes h to g_h, out[b] = bias + sum_{m>=64} relu*w[m-64]
// LAYER 1: h from g_h (FK=64), out[b] += sum_m relu*w[64+m]
template<int FK, int KTOT, int LAYER>
__global__ void __launch_bounds__(NTHREADS)
cin_layer_kernel(const float* __restrict__ x,
                 const float* __restrict__ W,     // [KTOT][128]
                 const float* __restrict__ dw,    // [192]
                 const float* __restrict__ db,    // [1]
                 float* __restrict__ out)         // [B]
{
    extern __shared__ float sm[];
    float* xs = sm;                                            // [39][128]
    float* hs = (LAYER == 0) ? sm : sm + 39 * 128;             // [FK][128]
    float* As = (LAYER == 0) ? (sm + 39 * 128)
                             : (sm + 39 * 128 + 64 * 128);     // [BK][128]
    float* Bs = As + BK * 128;                                 // [BK][128]
    float* s_out = Bs + BK * 128;                              // [8]

    const int tid = threadIdx.x;
    const int tx = tid & 15;        // 0..15 -> col group
    const int ty = tid >> 4;        // 0..15 -> row group
    const int rb = ty * 8;          // row base (b_local*16 + d)
    const int cb = tx * 8;          // col base (m)
    const int b0 = blockIdx.x * 8;  // first batch of this block

    // ---- load x into smem: xs[i][row], row = b_local*16 + d ----
    for (int e = tid; e < 39 * 128; e += NTHREADS) {
        int i = e >> 7;
        int row = e & 127;
        int bl = row >> 4;
        int d = row & 15;
        xs[e] = x[(b0 + bl) * (F0N * DN) + i * DN + d];
    }
    // ---- load h into smem (layer 1 only): hs[j][row] ----
    if (LAYER == 1) {
        for (int e = tid; e < 64 * 128; e += NTHREADS) {
            int j = e >> 7;
            int row = e & 127;
            int bl = row >> 4;
            int d = row & 15;
            hs[e] = g_h[(b0 + bl) * (64 * DN) + j * DN + d];
        }
    }

    float acc[8][8];
#pragma unroll
    for (int r = 0; r < 8; r++)
#pragma unroll
        for (int c = 0; c < 8; c++) acc[r][c] = 0.0f;

    const int nChunks = (KTOT + BK - 1) / BK;
    for (int ch = 0; ch < nChunks; ch++) {
        const int k0 = ch * BK;
        __syncthreads();  // previous compute done (and iter0: xs/hs visible)

        // ---- build A chunk: As[kk][row] = xs[i][row] * hs[j][row], k = i*FK + j
#pragma unroll
        for (int g = 0; g < 2; g++) {
            int idx4 = tid + g * NTHREADS;          // 0..511
            int kk = idx4 >> 5;                     // 0..15
            int r4 = (idx4 & 31) << 2;              // 0,4,...,124
            int k = k0 + kk;
            float4 v;
            if (k < KTOT) {
                int i = k / FK;
                int j = k - i * FK;
                float4 xa = *(const float4*)&xs[i * 128 + r4];
                float4 ha = *(const float4*)&hs[j * 128 + r4];
                v = make_float4(xa.x * ha.x, xa.y * ha.y, xa.z * ha.z, xa.w * ha.w);
            } else {
                v = make_float4(0.f, 0.f, 0.f, 0.f);
            }
            *(float4*)&As[kk * 128 + r4] = v;
        }
        // ---- load W chunk: Bs[kk][m] ----
#pragma unroll
        for (int g = 0; g < 2; g++) {
            int idx4 = tid + g * NTHREADS;
            int kk = idx4 >> 5;
            int m4 = (idx4 & 31) << 2;
            int k = k0 + kk;
            float4 v = make_float4(0.f, 0.f, 0.f, 0.f);
            if (k < KTOT) v = *(const float4*)&W[k * 128 + m4];
            *(float4*)&Bs[kk * 128 + m4] = v;
        }
        __syncthreads();

        // ---- 128x128x16 compute, 8x8 per thread ----
#pragma unroll
        for (int kk = 0; kk < BK; kk++) {
            float4 a0 = *(const float4*)&As[kk * 128 + rb];
            float4 a1 = *(const float4*)&As[kk * 128 + rb + 4];
            float4 bb0 = *(const float4*)&Bs[kk * 128 + cb];
            float4 bb1 = *(const float4*)&Bs[kk * 128 + cb + 4];
            float av[8] = {a0.x, a0.y, a0.z, a0.w, a1.x, a1.y, a1.z, a1.w};
            float bv[8] = {bb0.x, bb0.y, bb0.z, bb0.w, bb1.x, bb1.y, bb1.z, bb1.w};
#pragma unroll
            for (int r = 0; r < 8; r++)
#pragma unroll
                for (int c = 0; c < 8; c++)
                    acc[r][c] = fmaf(av[r], bv[c], acc[r][c]);
        }
    }

    // ---- epilogue: relu, store h (layer 0), weighted sum over (m, d) per batch ----
    const int b_local = ty >> 1;        // rows rb..rb+7 all within one batch
    const int d0 = rb & 15;             // 0 or 8
    const int b = b0 + b_local;

    float wv[8];
#pragma unroll
    for (int c = 0; c < 8; c++) {
        int m = cb + c;
        if (LAYER == 0)
            wv[c] = (m >= 64) ? dw[m - 64] : 0.0f;
        else
            wv[c] = dw[64 + m];
    }

    float partial = 0.0f;
#pragma unroll
    for (int r = 0; r < 8; r++) {
#pragma unroll
        for (int c = 0; c < 8; c++) {
            float v = fmaxf(acc[r][c], 0.0f);
            if (LAYER == 0 && cb < 64)
                g_h[b * (64 * DN) + (cb + c) * DN + (d0 + r)] = v;
            partial = fmaf(v, wv[c], partial);
        }
    }

    if (tid < 8) s_out[tid] = 0.0f;
    __syncthreads();
    atomicAdd(&s_out[b_local], partial);
    __syncthreads();
    if (tid < 8) {
        if (LAYER == 0)
            out[b0 + tid] = s_out[tid] + db[0];
        else
            out[b0 + tid] += s_out[tid];
    }
}

extern "C" void kernel_launch(void* const* d_in, const int* in_sizes, int n_in,
                              void* d_out, int out_size)
{
    const float* x  = (const float*)d_in[0];   // [4096][39][16]
    const float* f0 = (const float*)d_in[1];   // [1521][128]
    const float* f1 = (const float*)d_in[2];   // [2496][128]
    const float* dw = (const float*)d_in[3];   // [192]
    const float* db = (const float*)d_in[4];   // [1]
    float* out = (float*)d_out;                // [4096]

    const int smem0 = (39 * 128 + BK * 128 + BK * 128 + 8) * (int)sizeof(float);
    const int smem1 = (39 * 128 + 64 * 128 + BK * 128 + BK * 128 + 8) * (int)sizeof(float);

    // layer-1 needs >48KB dynamic smem
    cudaFuncSetAttribute(cin_layer_kernel<64, K1TOT, 1>,
                         cudaFuncAttributeMaxDynamicSharedMemorySize, smem1);

    dim3 grid(B_TOT / 8);
    dim3 block(NTHREADS);
    cin_layer_kernel<39, K0TOT, 0><<<grid, block, smem0>>>(x, f0, dw, db, out);
    cin_layer_kernel<64, K1TOT, 1><<<grid, block, smem1>>>(x, f1, dw, db, out);
}

// round 6
// speedup vs baseline: 1.9116x; 1.9116x over previous
#include <cuda_runtime.h>
#include <cuda_bf16.h>
#include <stdint.h>

// ---------------- problem constants ----------------
#define B_TOT   4096
#define F0N     39
#define DN      16
#define NT      256

#define K0TOT   1521      // 39*39
#define K0PAD   1536      // 24 chunks of 64
#define K1TOT   2496      // 39*64
#define K1PAD   2496      // 39 chunks of 64

#define BK      64        // K per chunk (bf16 elems)
#define BKP     72        // padded row length (bf16) for A/B tiles -> 144B stride
#define IPAD    41        // xs_T row stride (floats), odd vs 32 banks
#define JPAD    65        // hs_T row stride (floats)

// ---------------- global scratch ----------------
__device__ float         g_h[B_TOT * 64 * DN];
__device__ __nv_bfloat16 g_w0hi[128 * K0PAD];
__device__ __nv_bfloat16 g_w0lo[128 * K0PAD];
__device__ __nv_bfloat16 g_w1hi[128 * K1PAD];
__device__ __nv_bfloat16 g_w1lo[128 * K1PAD];

// ---------------- PTX helpers (all sm_80-era, safe for compute_103) ----------------
__device__ __forceinline__ uint32_t smem_to_u32(const void* p) {
    uint32_t a;
    asm("{ .reg .u64 t; cvta.to.shared.u64 t, %1; cvt.u32.u64 %0, t; }" : "=r"(a) : "l"(p));
    return a;
}

__device__ __forceinline__ void ldsm4(uint32_t* r, uint32_t addr) {
    asm volatile("ldmatrix.sync.aligned.m8n8.x4.shared.b16 {%0,%1,%2,%3}, [%4];"
        : "=r"(r[0]), "=r"(r[1]), "=r"(r[2]), "=r"(r[3]) : "r"(addr));
}

__device__ __forceinline__ void mma_bf16(float* c, const uint32_t* a, uint32_t b0, uint32_t b1) {
    asm volatile(
        "mma.sync.aligned.m16n8k16.row.col.f32.bf16.bf16.f32 "
        "{%0,%1,%2,%3}, {%4,%5,%6,%7}, {%8,%9}, {%0,%1,%2,%3};"
        : "+f"(c[0]), "+f"(c[1]), "+f"(c[2]), "+f"(c[3])
        : "r"(a[0]), "r"(a[1]), "r"(a[2]), "r"(a[3]), "r"(b0), "r"(b1));
}

#define CP_ASYNC16(saddr, gptr) \
    asm volatile("cp.async.cg.shared.global [%0], [%1], 16;" \
        :: "r"((uint32_t)(saddr)), "l"(gptr))
#define CP_COMMIT()  asm volatile("cp.async.commit_group;" ::: "memory")
#define CP_WAIT0()   asm volatile("cp.async.wait_group 0;"  ::: "memory")

// ---------------- W pre-split: f[k][128] -> g_w{hi,lo} [n=128][KPAD], zero-padded ----------------
template<int LAYER>
__global__ void __launch_bounds__(256)
convert_w_kernel(const float* __restrict__ f)
{
    constexpr int KTOT = (LAYER == 0) ? K0TOT : K1TOT;
    constexpr int KPAD = (LAYER == 0) ? K0PAD : K1PAD;
    __nv_bfloat16* whi = (LAYER == 0) ? g_w0hi : g_w1hi;
    __nv_bfloat16* wlo = (LAYER == 0) ? g_w0lo : g_w1lo;

    int idx = blockIdx.x * blockDim.x + threadIdx.x;
    if (idx >= 128 * KPAD) return;
    int n = idx / KPAD;
    int k = idx - n * KPAD;
    float v = (k < KTOT) ? f[k * 128 + n] : 0.0f;
    __nv_bfloat16 h = __float2bfloat16_rn(v);
    float r = v - __bfloat162float(h);
    whi[idx] = h;
    wlo[idx] = __float2bfloat16_rn(r);
}

// ---------------- main fused layer kernel (classic HMMA path) ----------------
// LAYER 0: h == x (FK=39), writes relu(z[:, :64]) to g_h, out = bias + sum z[:,64:]*dw[0:64]
// LAYER 1: h from g_h (FK=64), out += sum z * dw[64:192]
template<int FK, int KTOT, int KPAD, int LAYER>
__global__ void __launch_bounds__(NT)
cin_mma_kernel(const float* __restrict__ x,
               const float* __restrict__ dw,
               const float* __restrict__ db,
               float* __restrict__ out)
{
    extern __shared__ char smem[];

    constexpr int OFF_DW   = 0;                    // 192 floats
    constexpr int OFF_SOUT = 768;                  // 8 floats
    constexpr int OFF_XT   = 1024;                 // [128][IPAD] floats
    constexpr int XT_BYTES = 128 * IPAD * 4;       // 20992
    constexpr int OFF_HT   = OFF_XT + XT_BYTES;    // [128][JPAD] floats (layer 1)
    constexpr int HT_BYTES = (LAYER == 1) ? 128 * JPAD * 4 : 0;
    constexpr int OFF_A    = ((OFF_HT + HT_BYTES + 1023) / 1024) * 1024;
    constexpr int TILE_B   = 128 * BKP * 2;        // 18432
    constexpr int OFF_AHI  = OFF_A;
    constexpr int OFF_ALO  = OFF_A + TILE_B;
    constexpr int OFF_BHI  = OFF_A + 2 * TILE_B;
    constexpr int OFF_BLO  = OFF_A + 3 * TILE_B;
    constexpr int NCHUNKS  = KPAD / BK;

    const __nv_bfloat16* __restrict__ whi = (LAYER == 0) ? g_w0hi : g_w1hi;
    const __nv_bfloat16* __restrict__ wlo = (LAYER == 0) ? g_w0lo : g_w1lo;

    const uint32_t smem_u = smem_to_u32(smem);
    float* s_dw  = (float*)(smem + OFF_DW);
    float* s_out = (float*)(smem + OFF_SOUT);
    float* xt    = (float*)(smem + OFF_XT);
    float* ht    = (LAYER == 0) ? xt : (float*)(smem + OFF_HT);
    constexpr int HSTR = (LAYER == 0) ? IPAD : JPAD;

    const int tid  = threadIdx.x;
    const int wid  = tid >> 5;
    const int lane = tid & 31;
    const int b0   = blockIdx.x * 8;

    // ---- stage x transposed: xt[row][i], row = bl*16 + d ----
    for (int e = tid; e < 8 * F0N * DN; e += NT) {
        int bl = e / (F0N * DN);
        int rem = e - bl * (F0N * DN);
        int i = rem >> 4, d = rem & 15;
        xt[(bl * 16 + d) * IPAD + i] = x[(size_t)(b0) * (F0N * DN) + e];
    }
    // ---- stage h transposed (layer 1): ht[row][j] ----
    if (LAYER == 1) {
        for (int e = tid; e < 8 * 64 * 16; e += NT) {
            int bl = e >> 10;
            int j  = (e >> 4) & 63;
            int d  = e & 15;
            ht[(bl * 16 + d) * JPAD + j] = g_h[(size_t)b0 * 1024 + e];
        }
    }
    if (tid < 192) s_dw[tid] = dw[tid];
    if (tid < 8)   s_out[tid] = 0.0f;
    __syncthreads();

    // warp tiling: 4 (M) x 2 (N); warp tile 32 x 64
    const int wm = wid >> 1;
    const int wn = wid & 1;
    const int m0 = wm * 32;
    const int n0 = wn * 64;

    float acc[2][8][4];
#pragma unroll
    for (int mt = 0; mt < 2; mt++)
#pragma unroll
        for (int nt = 0; nt < 8; nt++)
#pragma unroll
            for (int r = 0; r < 4; r++) acc[mt][nt][r] = 0.0f;

    const int srow = tid >> 3;     // 0..31 (+p*32)
    const int skt  = tid & 7;      // 0..7 (8 bf16 each)

    for (int ch = 0; ch < NCHUNKS; ch++) {
        const int k0 = ch * BK;

        // ---- B chunk via cp.async (pre-split bf16 [n][KPAD]) ----
#pragma unroll
        for (int p = 0; p < 4; p++) {
            int n = srow + p * 32;
            uint32_t so = (uint32_t)(n * (BKP * 2) + skt * 16);
            CP_ASYNC16(smem_u + OFF_BHI + so, whi + (size_t)n * KPAD + k0 + skt * 8);
            CP_ASYNC16(smem_u + OFF_BLO + so, wlo + (size_t)n * KPAD + k0 + skt * 8);
        }
        CP_COMMIT();

        // ---- build A chunk (hi/lo bf16 split) into padded row-major smem ----
#pragma unroll
        for (int p = 0; p < 4; p++) {
            int row = srow + p * 32;
            int kb  = k0 + skt * 8;
            const float* xr = xt + row * IPAD;
            const float* hr = ht + row * HSTR;
            uint32_t hp[4], lp[4];
#pragma unroll
            for (int v = 0; v < 4; v++) {
                float p0 = 0.0f, p1 = 0.0f;
                int ka = kb + 2 * v;
                if (KPAD == KTOT || ka < KTOT) {
                    int i = ka / FK, j = ka - i * FK;
                    p0 = xr[i] * hr[j];
                }
                if (KPAD == KTOT || (ka + 1) < KTOT) {
                    int i = (ka + 1) / FK, j = (ka + 1) - i * FK;
                    p1 = xr[i] * hr[j];
                }
                __nv_bfloat16 h0 = __float2bfloat16_rn(p0);
                __nv_bfloat16 h1 = __float2bfloat16_rn(p1);
                __nv_bfloat16 e0 = __float2bfloat16_rn(p0 - __bfloat162float(h0));
                __nv_bfloat16 e1 = __float2bfloat16_rn(p1 - __bfloat162float(h1));
                hp[v] = (uint32_t)__bfloat16_as_ushort(h0) | ((uint32_t)__bfloat16_as_ushort(h1) << 16);
                lp[v] = (uint32_t)__bfloat16_as_ushort(e0) | ((uint32_t)__bfloat16_as_ushort(e1) << 16);
            }
            uint32_t so = (uint32_t)(row * (BKP * 2) + skt * 16);
            *(uint4*)(smem + OFF_AHI + so) = make_uint4(hp[0], hp[1], hp[2], hp[3]);
            *(uint4*)(smem + OFF_ALO + so) = make_uint4(lp[0], lp[1], lp[2], lp[3]);
        }

        CP_WAIT0();
        __syncthreads();

        // ---- compute: 4 k16-steps, ldmatrix + mma ----
        const int lrow = (lane & 7) + ((lane >> 3) & 1) * 8;   // row within 16-row tile
        const int lkb  = (lane >> 4) * 16;                     // 0 or 16 bytes (8 bf16)
#pragma unroll
        for (int ks = 0; ks < 4; ks++) {
            const uint32_t kcb = (uint32_t)(ks * 32 + lkb);    // byte offset in row
            uint32_t ah[2][4], al[2][4];
#pragma unroll
            for (int mt = 0; mt < 2; mt++) {
                uint32_t ra = (uint32_t)((m0 + mt * 16 + lrow) * (BKP * 2)) + kcb;
                ldsm4(ah[mt], smem_u + OFF_AHI + ra);
                ldsm4(al[mt], smem_u + OFF_ALO + ra);
            }
#pragma unroll
            for (int nt2 = 0; nt2 < 4; nt2++) {
                uint32_t rb = (uint32_t)((n0 + nt2 * 16 + lrow) * (BKP * 2)) + kcb;
                uint32_t bh[4], blr[4];
                ldsm4(bh,  smem_u + OFF_BHI + rb);
                ldsm4(blr, smem_u + OFF_BLO + rb);
#pragma unroll
                for (int mt = 0; mt < 2; mt++) {
#pragma unroll
                    for (int sub = 0; sub < 2; sub++) {
                        float* c = acc[mt][nt2 * 2 + sub];
                        mma_bf16(c, ah[mt], bh[sub],  bh[sub + 2]);   // hi*hi
                        mma_bf16(c, ah[mt], blr[sub], blr[sub + 2]);  // hi*lo
                        mma_bf16(c, al[mt], bh[sub],  bh[sub + 2]);   // lo*hi
                    }
                }
            }
        }
        __syncthreads();   // protect smem reuse next chunk
    }

    // ---- epilogue: relu, h-store (layer 0), weighted reduce ----
    const int qrow = lane >> 2;        // 0..7
    const int qcol = (lane & 3) * 2;   // 0,2,4,6
#pragma unroll
    for (int mt = 0; mt < 2; mt++) {
        const int bl = wm * 2 + mt;
        const int b  = b0 + bl;
        float partial = 0.0f;
#pragma unroll
        for (int nt = 0; nt < 8; nt++) {
#pragma unroll
            for (int r = 0; r < 4; r++) {
                int d = qrow + 8 * (r >> 1);
                int n = n0 + nt * 8 + qcol + (r & 1);
                float v = fmaxf(acc[mt][nt][r], 0.0f);
                if (LAYER == 0) {
                    if (n < 64)
                        g_h[((size_t)b * 64 + n) * 16 + d] = v;
                    else
                        partial = fmaf(v, s_dw[n - 64], partial);
                } else {
                    partial = fmaf(v, s_dw[64 + n], partial);
                }
            }
        }
        atomicAdd(&s_out[bl], partial);
    }
    __syncthreads();
    if (tid < 8) {
        if (LAYER == 0) out[b0 + tid] = s_out[tid] + db[0];
        else            out[b0 + tid] += s_out[tid];
    }
}

// ---------------- launch ----------------
extern "C" void kernel_launch(void* const* d_in, const int* in_sizes, int n_in,
                              void* d_out, int out_size)
{
    const float* x  = (const float*)d_in[0];   // [4096][39][16]
    const float* f0 = (const float*)d_in[1];   // [1521][128]
    const float* f1 = (const float*)d_in[2];   // [2496][128]
    const float* dw = (const float*)d_in[3];   // [192]
    const float* db = (const float*)d_in[4];   // [1]
    float* out = (float*)d_out;                // [4096]

    // pre-split W into bf16 hi/lo, transposed to [n][KPAD], zero-padded
    convert_w_kernel<0><<<(128 * K0PAD + 255) / 256, 256>>>(f0);
    convert_w_kernel<1><<<(128 * K1PAD + 255) / 256, 256>>>(f1);

    constexpr int XT_BYTES = 128 * IPAD * 4;
    constexpr int OFF_A0 = ((1024 + XT_BYTES + 1023) / 1024) * 1024;
    constexpr int OFF_A1 = ((1024 + XT_BYTES + 128 * JPAD * 4 + 1023) / 1024) * 1024;
    constexpr int TILE_B = 128 * BKP * 2;
    const int smem0 = OFF_A0 + 4 * TILE_B;   // ~96 KB
    const int smem1 = OFF_A1 + 4 * TILE_B;   // ~129 KB

    cudaFuncSetAttribute(cin_mma_kernel<39, K0TOT, K0PAD, 0>,
                         cudaFuncAttributeMaxDynamicSharedMemorySize, smem0);
    cudaFuncSetAttribute(cin_mma_kernel<64, K1TOT, K1PAD, 1>,
                         cudaFuncAttributeMaxDynamicSharedMemorySize, smem1);

    dim3 grid(B_TOT / 8);
    dim3 block(NT);
    cin_mma_kernel<39, K0TOT, K0PAD, 0><<<grid, block, smem0>>>(x, dw, db, out);
    cin_mma_kernel<64, K1TOT, K1PAD, 1><<<grid, block, smem1>>>(x, dw, db, out);
}